// round 3
// baseline (speedup 1.0000x reference)
#include <cuda_runtime.h>
#include <cstdint>

// CARAFE: B=8, C=256, H=W=64, K=5, UP=2.
// out[b,c,2h+i,2w+j] = sum_{ki,kj} km[b, (i*2+j)*25 + ki*5+kj, h, w] * x[b,c,h+ki-2,w+kj-2]
//
// Strategy:
//  - grid (B*H=512, 2 channel halves), block 128 = 64 w-columns x 2 channel slices
//  - per-thread: 100 weights for its (h,w) pixel held in REGISTERS (reused across
//    all channels) -> inner loop is 25 LDS + 100 FMA per channel (FMA:LDS = 4:1)
//  - input halo rows (5 x 68) staged in smem, 8 channels per __syncthreads pair
//  - 4 sub-pixel outputs per thread, stored as two coalesced float2

namespace {
constexpr int Hc = 64, Wc = 64, Cc = 256, Bc = 8;
constexpr int Kk = 5, KK = 25, QQ = 100;     // kernel, k*k, up^2*k*k
constexpr int CPC = 4;                        // channels staged per slice per sync
constexpr int SLICES = 2;
constexpr int THREADS = 128;
constexpr int ROWE = Wc + Kk - 1;             // 68 staged columns (halo)
constexpr int CH_ELEMS = Kk * ROWE;           // 340 floats per staged channel
}

__global__ __launch_bounds__(THREADS, 3)
void carafe_kernel(const float* __restrict__ x,
                   const float* __restrict__ km,
                   float* __restrict__ out)
{
    const int bh = blockIdx.x;           // 0..511
    const int b  = bh >> 6;
    const int h  = bh & 63;
    const int cbase = blockIdx.y << 7;   // 0 or 128
    const int tid = threadIdx.x;
    const int w   = tid & 63;
    const int s   = tid >> 6;            // channel slice 0/1

    __shared__ float sbuf[SLICES * CPC][Kk][ROWE];   // 8 x 5 x 68 floats

    // ---- Load this pixel's 100 reassembly weights into registers ----
    // km[b,q,h,w] = km[ b*100*4096 + q*4096 + h*64 + w ]
    float wreg[QQ];
    const float* kmp = km + ((size_t)b * QQ * Hc + h) * Wc + w;
    #pragma unroll
    for (int q = 0; q < QQ; q++)
        wreg[q] = __ldg(kmp + (size_t)q * (Hc * Wc));

    const float* xb = x   + (size_t)b * Cc * Hc * Wc;
    float*       ob = out + (size_t)b * Cc * (Hc * 2) * (Wc * 2);

    for (int t0 = 0; t0 < 64; t0 += CPC) {
        __syncthreads();
        // ---- Stage 8 channels' halo rows into smem (coalesced) ----
        for (int e = tid; e < SLICES * CPC * CH_ELEMS; e += THREADS) {
            int ci  = e / CH_ELEMS;               // 0..7
            int rem = e - ci * CH_ELEMS;
            int r   = rem / ROWE;                 // 0..4
            int col = rem - r * ROWE;             // 0..67
            int gr  = h - 2 + r;
            int gc  = col - 2;
            int c   = cbase + ((ci >> 2) << 6) + t0 + (ci & 3);
            float v = 0.f;
            if ((unsigned)gr < (unsigned)Hc && (unsigned)gc < (unsigned)Wc)
                v = __ldg(xb + ((size_t)c * Hc + gr) * Wc + gc);
            sbuf[ci][r][col] = v;
        }
        __syncthreads();

        // ---- Compute CPC channels for this thread's slice ----
        #pragma unroll
        for (int kch = 0; kch < CPC; kch++) {
            const int ci = s * CPC + kch;
            const int c  = cbase + (s << 6) + t0 + kch;

            float xv[KK];
            #pragma unroll
            for (int r = 0; r < Kk; r++)
                #pragma unroll
                for (int j = 0; j < Kk; j++)
                    xv[r * Kk + j] = sbuf[ci][r][w + j];

            float acc[4];
            #pragma unroll
            for (int u = 0; u < 4; u++) {
                float a = 0.f;
                #pragma unroll
                for (int k = 0; k < KK; k++)
                    a = fmaf(wreg[u * KK + k], xv[k], a);
                acc[u] = a;
            }

            // sub-pixel u = i*2 + j -> out row 2h+i, col 2w+j
            float* orow0 = ob + ((size_t)c * 128 + 2 * h    ) * 128 + 2 * w;
            float* orow1 = ob + ((size_t)c * 128 + 2 * h + 1) * 128 + 2 * w;
            *reinterpret_cast<float2*>(orow0) = make_float2(acc[0], acc[1]);
            *reinterpret_cast<float2*>(orow1) = make_float2(acc[2], acc[3]);
        }
    }
}

extern "C" void kernel_launch(void* const* d_in, const int* in_sizes, int n_in,
                              void* d_out, int out_size)
{
    const float* x  = (const float*)d_in[0];   // input [8,256,64,64]
    const float* km = (const float*)d_in[1];   // kernel_map [8,100,64,64]
    float* out = (float*)d_out;                // [8,256,128,128]

    dim3 grid(Bc * Hc, 2);
    carafe_kernel<<<grid, THREADS>>>(x, km, out);
}